// round 1
// baseline (speedup 1.0000x reference)
#include <cuda_runtime.h>
#include <cuda_fp16.h>
#include <mma.h>

using namespace nvcuda;

#define B_TOT   8192
#define NTOK    49
#define CDIM    192
#define NH      6
#define HDIM    32
#define SCALE_F 0.17677669529663687f   // 1/sqrt(32)

// fp16 copies of the weights (converted by conv_w each call; deterministic)
__device__ __align__(16) __half g_wqkv[CDIM * 3 * CDIM];   // [192][576] row-major
__device__ __align__(16) __half g_wproj[CDIM * CDIM];      // [192][192] row-major

__global__ void conv_w(const float* __restrict__ wq, const float* __restrict__ wp) {
    int i = blockIdx.x * 256 + threadIdx.x;
    if (i < CDIM * 3 * CDIM) g_wqkv[i]  = __float2half_rn(wq[i]);
    if (i < CDIM * CDIM)     g_wproj[i] = __float2half_rn(wp[i]);
}

// ---- shared memory layout (byte offsets, all 128B aligned) ----
// xs   : half  [64][200]   @ 0       25600 B   (x, fp16, rows >=49 zero)
// qkvs : half  [64][104]   @ 25600   13312 B   (Q|K|V for current head)
// R    : union             @ 38912   18432 B   (Ss fp32 [64][72] / stage 8x256 f32 / wp half [32][192])
// Ps   : half  [64][72]    @ 57344    9216 B
// Os   : half  [64][40]    @ 66560    5120 B
// ws   : half  [192][104]  @ 71680   39936 B   (per-head qkv weight slice)
// msk  : float [64]        @ 111616    256 B
#define SMEM_BYTES 111872

__global__ void __launch_bounds__(256, 2)
attn_kernel(const float* __restrict__ x, const int* __restrict__ mask,
            const float* __restrict__ bqkv, const float* __restrict__ bproj,
            float* __restrict__ out)
{
    extern __shared__ __align__(128) char smem[];
    __half* xs    = (__half*)(smem);                 // ld 200
    __half* qkvs  = (__half*)(smem + 25600);         // ld 104
    float*  R     = (float*) (smem + 38912);
    float*  Ss    = R;                               // ld 72
    float*  stage = R;                               // 8 warps x 256 floats
    __half* wp    = (__half*)R;                      // ld 192
    __half* Ps    = (__half*)(smem + 57344);         // ld 72
    __half* Os    = (__half*)(smem + 66560);         // ld 40
    __half* ws    = (__half*)(smem + 71680);         // ld 104
    float*  msk   = (float*) (smem + 111616);

    const int b    = blockIdx.x;
    const int tid  = threadIdx.x;
    const int w    = tid >> 5;
    const int lane = tid & 31;

    // ---- load x[b] -> fp16 smem, pad rows 49..63 with zeros ----
    const float* xb = x + (size_t)b * (NTOK * CDIM);
    for (int i = tid; i < 64 * CDIM; i += 256) {
        int r = i / CDIM, c = i - r * CDIM;
        float v = (r < NTOK) ? xb[r * CDIM + c] : 0.0f;
        xs[r * 200 + c] = __float2half_rn(v);
    }
    if (tid < 64) {
        int valid = (tid < NTOK) ? (mask[b * NTOK + tid] != 0) : 0;
        msk[tid] = valid ? 1.0f : 0.0f;
    }

    // persistent proj accumulators: warp w owns m-tile (w>>1), n-tiles n0..n0+5
    wmma::fragment<wmma::accumulator, 16, 16, 16, float> cacc[6];
    #pragma unroll
    for (int j = 0; j < 6; j++) wmma::fill_fragment(cacc[j], 0.0f);
    const int mM = w >> 1;
    const int n0 = (w & 1) * 6;

    for (int h = 0; h < NH; h++) {
        __syncthreads();  // guards R(wp), qkvs, Os, ws reuse from previous head

        // ---- stage per-head qkv weight slice: ws[192][96] (Q|K|V cols of head h) ----
        for (int i = tid; i < 2304; i += 256) {        // 192 rows * 12 int4
            int row = i / 12, jv = i - row * 12;
            int sec = jv >> 2, v8 = jv & 3;
            const int4* s = (const int4*)(g_wqkv + row * 576 + sec * 192 + h * 32 + v8 * 8);
            *(int4*)(ws + row * 104 + sec * 32 + v8 * 8) = *s;
        }
        __syncthreads();

        // ---- GEMM1: qkvs[64][96] = xs[64][192] @ ws[192][96] + bias ----
        for (int t = w; t < 24; t += 8) {
            int m = t / 6, n = t - m * 6;
            wmma::fragment<wmma::matrix_a, 16, 16, 16, __half, wmma::row_major> a;
            wmma::fragment<wmma::matrix_b, 16, 16, 16, __half, wmma::row_major> bf;
            wmma::fragment<wmma::accumulator, 16, 16, 16, float> c;
            wmma::fill_fragment(c, 0.0f);
            #pragma unroll
            for (int kt = 0; kt < 12; kt++) {
                wmma::load_matrix_sync(a, xs + m * 16 * 200 + kt * 16, 200);
                wmma::load_matrix_sync(bf, ws + kt * 16 * 104 + n * 16, 104);
                wmma::mma_sync(c, a, bf, c);
            }
            float* st = stage + w * 256;
            wmma::store_matrix_sync(st, c, 16, wmma::mem_row_major);
            __syncwarp();
            int sec = n >> 1;
            int colbase = sec * 192 + h * 32 + (n & 1) * 16;
            for (int e = lane; e < 256; e += 32) {
                int rr = e >> 4, cc = e & 15;
                float v = st[e] + bqkv[colbase + cc];
                qkvs[(m * 16 + rr) * 104 + n * 16 + cc] = __float2half_rn(v);
            }
            __syncwarp();
        }
        __syncthreads();

        // ---- GEMM2: Ss[64][64] = (Q @ K^T) * scale ----
        for (int t = w; t < 16; t += 8) {
            int m = t >> 2, n = t & 3;
            wmma::fragment<wmma::matrix_a, 16, 16, 16, __half, wmma::row_major> a;
            wmma::fragment<wmma::matrix_b, 16, 16, 16, __half, wmma::col_major> bf;
            wmma::fragment<wmma::accumulator, 16, 16, 16, float> c;
            wmma::fill_fragment(c, 0.0f);
            #pragma unroll
            for (int kt = 0; kt < 2; kt++) {
                wmma::load_matrix_sync(a,  qkvs + m * 16 * 104 + kt * 16, 104);
                wmma::load_matrix_sync(bf, qkvs + n * 16 * 104 + 32 + kt * 16, 104);
                wmma::mma_sync(c, a, bf, c);
            }
            #pragma unroll
            for (int i = 0; i < c.num_elements; i++) c.x[i] *= SCALE_F;
            wmma::store_matrix_sync(Ss + m * 16 * 72 + n * 16, c, 72, wmma::mem_row_major);
        }
        __syncthreads();

        // ---- masked softmax rows -> Ps fp16 (invalid cols & pad rows -> 0) ----
        for (int r = w; r < 64; r += 8) {
            if (r < NTOK) {
                float v0 = (msk[lane]      != 0.0f) ? Ss[r * 72 + lane]      : -1e30f;
                float v1 = (msk[lane + 32] != 0.0f) ? Ss[r * 72 + lane + 32] : -1e30f;
                float mx = fmaxf(v0, v1);
                #pragma unroll
                for (int o = 16; o > 0; o >>= 1) mx = fmaxf(mx, __shfl_xor_sync(0xffffffffu, mx, o));
                float e0 = __expf(v0 - mx), e1 = __expf(v1 - mx);
                float sm = e0 + e1;
                #pragma unroll
                for (int o = 16; o > 0; o >>= 1) sm += __shfl_xor_sync(0xffffffffu, sm, o);
                float inv = 1.0f / sm;
                Ps[r * 72 + lane]      = __float2half_rn(e0 * inv);
                Ps[r * 72 + lane + 32] = __float2half_rn(e1 * inv);
            } else {
                Ps[r * 72 + lane]      = __float2half_rn(0.0f);
                Ps[r * 72 + lane + 32] = __float2half_rn(0.0f);
            }
        }
        __syncthreads();

        // ---- GEMM3: Os[64][32] = Ps[64][64] @ V[64][32] ----
        {
            int m = w >> 1, n = w & 1;
            wmma::fragment<wmma::matrix_a, 16, 16, 16, __half, wmma::row_major> a;
            wmma::fragment<wmma::matrix_b, 16, 16, 16, __half, wmma::row_major> bf;
            wmma::fragment<wmma::accumulator, 16, 16, 16, float> c;
            wmma::fill_fragment(c, 0.0f);
            #pragma unroll
            for (int kt = 0; kt < 4; kt++) {
                wmma::load_matrix_sync(a,  Ps + m * 16 * 72 + kt * 16, 72);
                wmma::load_matrix_sync(bf, qkvs + kt * 16 * 104 + 64 + n * 16, 104);
                wmma::mma_sync(c, a, bf, c);
            }
            float* st = stage + w * 256;
            wmma::store_matrix_sync(st, c, 16, wmma::mem_row_major);
            __syncwarp();
            for (int e = lane; e < 256; e += 32) {
                int rr = e >> 4, cc = e & 15;
                Os[(m * 16 + rr) * 40 + n * 16 + cc] = __float2half_rn(st[e]);
            }
        }
        __syncthreads();

        // ---- stage per-head proj weight slice: wp[32][192] = w_proj[h*32 .. h*32+31][:] ----
        for (int i = tid; i < 768; i += 256) {          // 32 rows * 24 int4
            int row = i / 24, v8 = i - row * 24;
            const int4* s = (const int4*)(g_wproj + (h * 32 + row) * 192 + v8 * 8);
            *(int4*)(wp + row * 192 + v8 * 8) = *s;
        }
        __syncthreads();

        // ---- GEMM4 (accumulate): cacc += Os[64][32] @ wp[32][192] ----
        #pragma unroll
        for (int j = 0; j < 6; j++) {
            wmma::fragment<wmma::matrix_a, 16, 16, 16, __half, wmma::row_major> a;
            wmma::fragment<wmma::matrix_b, 16, 16, 16, __half, wmma::row_major> bf;
            #pragma unroll
            for (int kt = 0; kt < 2; kt++) {
                wmma::load_matrix_sync(a,  Os + mM * 16 * 40 + kt * 16, 40);
                wmma::load_matrix_sync(bf, wp + kt * 16 * 192 + (n0 + j) * 16, 192);
                wmma::mma_sync(cacc[j], a, bf, cacc[j]);
            }
        }
    }

    __syncthreads();  // all warps done reading wp before stage slots are reused

    // ---- epilogue: + b_proj, store rows < 49 ----
    float* ob = out + (size_t)b * (NTOK * CDIM);
    #pragma unroll
    for (int j = 0; j < 6; j++) {
        float* st = stage + w * 256;
        wmma::store_matrix_sync(st, cacc[j], 16, wmma::mem_row_major);
        __syncwarp();
        int ncol = (n0 + j) * 16;
        for (int e = lane; e < 256; e += 32) {
            int rr = e >> 4, cc = e & 15;
            int r = mM * 16 + rr;
            if (r < NTOK) ob[r * CDIM + ncol + cc] = st[e] + bproj[ncol + cc];
        }
        __syncwarp();
    }
}

extern "C" void kernel_launch(void* const* d_in, const int* in_sizes, int n_in,
                              void* d_out, int out_size)
{
    (void)in_sizes; (void)n_in; (void)out_size;
    const float* x    = (const float*)d_in[0];
    const int*   mask = (const int*)  d_in[1];
    const float* wq   = (const float*)d_in[2];
    const float* bq   = (const float*)d_in[3];
    const float* wpj  = (const float*)d_in[4];
    const float* bp   = (const float*)d_in[5];
    float* out = (float*)d_out;

    conv_w<<<(CDIM * 3 * CDIM + 255) / 256, 256>>>(wq, wpj);

    cudaFuncSetAttribute(attn_kernel, cudaFuncAttributeMaxDynamicSharedMemorySize, SMEM_BYTES);
    attn_kernel<<<B_TOT, 256, SMEM_BYTES>>>(x, mask, bq, bp, out);
}

// round 2
// speedup vs baseline: 1.0010x; 1.0010x over previous
#include <cuda_runtime.h>
#include <cuda_fp16.h>
#include <mma.h>

using namespace nvcuda;

#define B_TOT   8192
#define NTOK    49
#define CDIM    192
#define NH      6
#define HDIM    32
#define SCALE_F 0.17677669529663687f   // 1/sqrt(32)

// fp16 copies of the weights (converted by conv_w each call; deterministic)
__device__ __align__(16) __half g_wqkv[CDIM * 3 * CDIM];   // [192][576] row-major
__device__ __align__(16) __half g_wproj[CDIM * CDIM];      // [192][192] row-major

__global__ void conv_w(const float* __restrict__ wq, const float* __restrict__ wp) {
    int i = blockIdx.x * 256 + threadIdx.x;
    if (i < CDIM * 3 * CDIM) g_wqkv[i]  = __float2half_rn(wq[i]);
    if (i < CDIM * CDIM)     g_wproj[i] = __float2half_rn(wp[i]);
}

// ---- shared memory layout (byte offsets, all 128B aligned) ----
// xs   : half  [64][200]   @ 0       25600 B   (x, fp16, rows >=49 zero)
// qkvs : half  [64][104]   @ 25600   13312 B   (Q|K|V for current head)
// R    : union             @ 38912   18432 B   (Ss fp32 [64][72] / stage 8x256 f32 / wp half [32][192])
// Ps   : half  [64][72]    @ 57344    9216 B
// Os   : half  [64][40]    @ 66560    5120 B
// ws   : half  [192][104]  @ 71680   39936 B   (per-head qkv weight slice)
// msk  : float [64]        @ 111616    256 B
#define SMEM_BYTES 111872

__global__ void __launch_bounds__(256, 2)
attn_kernel(const float* __restrict__ x, const int* __restrict__ mask,
            const float* __restrict__ bqkv, const float* __restrict__ bproj,
            float* __restrict__ out)
{
    extern __shared__ __align__(128) char smem[];
    __half* xs    = (__half*)(smem);                 // ld 200
    __half* qkvs  = (__half*)(smem + 25600);         // ld 104
    float*  R     = (float*) (smem + 38912);
    float*  Ss    = R;                               // ld 72
    float*  stage = R;                               // 8 warps x 256 floats
    __half* wp    = (__half*)R;                      // ld 192
    __half* Ps    = (__half*)(smem + 57344);         // ld 72
    __half* Os    = (__half*)(smem + 66560);         // ld 40
    __half* ws    = (__half*)(smem + 71680);         // ld 104
    float*  msk   = (float*) (smem + 111616);

    const int b    = blockIdx.x;
    const int tid  = threadIdx.x;
    const int w    = tid >> 5;
    const int lane = tid & 31;

    // ---- load x[b] -> fp16 smem, pad rows 49..63 with zeros ----
    const float* xb = x + (size_t)b * (NTOK * CDIM);
    for (int i = tid; i < 64 * CDIM; i += 256) {
        int r = i / CDIM, c = i - r * CDIM;
        float v = (r < NTOK) ? xb[r * CDIM + c] : 0.0f;
        xs[r * 200 + c] = __float2half_rn(v);
    }
    if (tid < 64) {
        int valid = (tid < NTOK) ? (mask[b * NTOK + tid] != 0) : 0;
        msk[tid] = valid ? 1.0f : 0.0f;
    }

    // persistent proj accumulators: warp w owns m-tile (w>>1), n-tiles n0..n0+5
    wmma::fragment<wmma::accumulator, 16, 16, 16, float> cacc[6];
    #pragma unroll
    for (int j = 0; j < 6; j++) wmma::fill_fragment(cacc[j], 0.0f);
    const int mM = w >> 1;
    const int n0 = (w & 1) * 6;

    for (int h = 0; h < NH; h++) {
        __syncthreads();  // guards R(wp), qkvs, Os, ws reuse from previous head

        // ---- stage per-head qkv weight slice: ws[192][96] (Q|K|V cols of head h) ----
        for (int i = tid; i < 2304; i += 256) {        // 192 rows * 12 int4
            int row = i / 12, jv = i - row * 12;
            int sec = jv >> 2, v8 = jv & 3;
            const int4* s = (const int4*)(g_wqkv + row * 576 + sec * 192 + h * 32 + v8 * 8);
            *(int4*)(ws + row * 104 + sec * 32 + v8 * 8) = *s;
        }
        __syncthreads();

        // ---- GEMM1: qkvs[64][96] = xs[64][192] @ ws[192][96] + bias ----
        for (int t = w; t < 24; t += 8) {
            int m = t / 6, n = t - m * 6;
            wmma::fragment<wmma::matrix_a, 16, 16, 16, __half, wmma::row_major> a;
            wmma::fragment<wmma::matrix_b, 16, 16, 16, __half, wmma::row_major> bf;
            wmma::fragment<wmma::accumulator, 16, 16, 16, float> c;
            wmma::fill_fragment(c, 0.0f);
            #pragma unroll
            for (int kt = 0; kt < 12; kt++) {
                wmma::load_matrix_sync(a, xs + m * 16 * 200 + kt * 16, 200);
                wmma::load_matrix_sync(bf, ws + kt * 16 * 104 + n * 16, 104);
                wmma::mma_sync(c, a, bf, c);
            }
            float* st = stage + w * 256;
            wmma::store_matrix_sync(st, c, 16, wmma::mem_row_major);
            __syncwarp();
            int sec = n >> 1;
            int colbase = sec * 192 + h * 32 + (n & 1) * 16;
            for (int e = lane; e < 256; e += 32) {
                int rr = e >> 4, cc = e & 15;
                float v = st[e] + bqkv[colbase + cc];
                qkvs[(m * 16 + rr) * 104 + n * 16 + cc] = __float2half_rn(v);
            }
            __syncwarp();
        }
        __syncthreads();

        // ---- GEMM2: Ss[64][64] = (Q @ K^T) * scale ----
        for (int t = w; t < 16; t += 8) {
            int m = t >> 2, n = t & 3;
            wmma::fragment<wmma::matrix_a, 16, 16, 16, __half, wmma::row_major> a;
            wmma::fragment<wmma::matrix_b, 16, 16, 16, __half, wmma::col_major> bf;
            wmma::fragment<wmma::accumulator, 16, 16, 16, float> c;
            wmma::fill_fragment(c, 0.0f);
            #pragma unroll
            for (int kt = 0; kt < 2; kt++) {
                wmma::load_matrix_sync(a,  qkvs + m * 16 * 104 + kt * 16, 104);
                wmma::load_matrix_sync(bf, qkvs + n * 16 * 104 + 32 + kt * 16, 104);
                wmma::mma_sync(c, a, bf, c);
            }
            #pragma unroll
            for (int i = 0; i < c.num_elements; i++) c.x[i] *= SCALE_F;
            wmma::store_matrix_sync(Ss + m * 16 * 72 + n * 16, c, 72, wmma::mem_row_major);
        }
        __syncthreads();

        // ---- masked softmax rows -> Ps fp16 (invalid cols & pad rows -> 0) ----
        for (int r = w; r < 64; r += 8) {
            if (r < NTOK) {
                float v0 = (msk[lane]      != 0.0f) ? Ss[r * 72 + lane]      : -1e30f;
                float v1 = (msk[lane + 32] != 0.0f) ? Ss[r * 72 + lane + 32] : -1e30f;
                float mx = fmaxf(v0, v1);
                #pragma unroll
                for (int o = 16; o > 0; o >>= 1) mx = fmaxf(mx, __shfl_xor_sync(0xffffffffu, mx, o));
                float e0 = __expf(v0 - mx), e1 = __expf(v1 - mx);
                float sm = e0 + e1;
                #pragma unroll
                for (int o = 16; o > 0; o >>= 1) sm += __shfl_xor_sync(0xffffffffu, sm, o);
                float inv = 1.0f / sm;
                Ps[r * 72 + lane]      = __float2half_rn(e0 * inv);
                Ps[r * 72 + lane + 32] = __float2half_rn(e1 * inv);
            } else {
                Ps[r * 72 + lane]      = __float2half_rn(0.0f);
                Ps[r * 72 + lane + 32] = __float2half_rn(0.0f);
            }
        }
        __syncthreads();

        // ---- GEMM3: Os[64][32] = Ps[64][64] @ V[64][32] ----
        {
            int m = w >> 1, n = w & 1;
            wmma::fragment<wmma::matrix_a, 16, 16, 16, __half, wmma::row_major> a;
            wmma::fragment<wmma::matrix_b, 16, 16, 16, __half, wmma::row_major> bf;
            wmma::fragment<wmma::accumulator, 16, 16, 16, float> c;
            wmma::fill_fragment(c, 0.0f);
            #pragma unroll
            for (int kt = 0; kt < 4; kt++) {
                wmma::load_matrix_sync(a,  Ps + m * 16 * 72 + kt * 16, 72);
                wmma::load_matrix_sync(bf, qkvs + kt * 16 * 104 + 64 + n * 16, 104);
                wmma::mma_sync(c, a, bf, c);
            }
            float* st = stage + w * 256;
            wmma::store_matrix_sync(st, c, 16, wmma::mem_row_major);
            __syncwarp();
            for (int e = lane; e < 256; e += 32) {
                int rr = e >> 4, cc = e & 15;
                Os[(m * 16 + rr) * 40 + n * 16 + cc] = __float2half_rn(st[e]);
            }
        }
        __syncthreads();

        // ---- stage per-head proj weight slice: wp[32][192] = w_proj[h*32 .. h*32+31][:] ----
        for (int i = tid; i < 768; i += 256) {          // 32 rows * 24 int4
            int row = i / 24, v8 = i - row * 24;
            const int4* s = (const int4*)(g_wproj + (h * 32 + row) * 192 + v8 * 8);
            *(int4*)(wp + row * 192 + v8 * 8) = *s;
        }
        __syncthreads();

        // ---- GEMM4 (accumulate): cacc += Os[64][32] @ wp[32][192] ----
        #pragma unroll
        for (int j = 0; j < 6; j++) {
            wmma::fragment<wmma::matrix_a, 16, 16, 16, __half, wmma::row_major> a;
            wmma::fragment<wmma::matrix_b, 16, 16, 16, __half, wmma::row_major> bf;
            #pragma unroll
            for (int kt = 0; kt < 2; kt++) {
                wmma::load_matrix_sync(a,  Os + mM * 16 * 40 + kt * 16, 40);
                wmma::load_matrix_sync(bf, wp + kt * 16 * 192 + (n0 + j) * 16, 192);
                wmma::mma_sync(cacc[j], a, bf, cacc[j]);
            }
        }
    }

    __syncthreads();  // all warps done reading wp before stage slots are reused

    // ---- epilogue: + b_proj, store rows < 49 ----
    float* ob = out + (size_t)b * (NTOK * CDIM);
    #pragma unroll
    for (int j = 0; j < 6; j++) {
        float* st = stage + w * 256;
        wmma::store_matrix_sync(st, cacc[j], 16, wmma::mem_row_major);
        __syncwarp();
        int ncol = (n0 + j) * 16;
        for (int e = lane; e < 256; e += 32) {
            int rr = e >> 4, cc = e & 15;
            int r = mM * 16 + rr;
            if (r < NTOK) ob[r * CDIM + ncol + cc] = st[e] + bproj[ncol + cc];
        }
        __syncwarp();
    }
}

extern "C" void kernel_launch(void* const* d_in, const int* in_sizes, int n_in,
                              void* d_out, int out_size)
{
    (void)in_sizes; (void)n_in; (void)out_size;
    const float* x    = (const float*)d_in[0];
    const int*   mask = (const int*)  d_in[1];
    const float* wq   = (const float*)d_in[2];
    const float* bq   = (const float*)d_in[3];
    const float* wpj  = (const float*)d_in[4];
    const float* bp   = (const float*)d_in[5];
    float* out = (float*)d_out;

    conv_w<<<(CDIM * 3 * CDIM + 255) / 256, 256>>>(wq, wpj);

    cudaFuncSetAttribute(attn_kernel, cudaFuncAttributeMaxDynamicSharedMemorySize, SMEM_BYTES);
    attn_kernel<<<B_TOT, 256, SMEM_BYTES>>>(x, mask, bq, bp, out);
}

// round 3
// speedup vs baseline: 1.3926x; 1.3912x over previous
#include <cuda_runtime.h>
#include <cuda_fp16.h>
#include <mma.h>

using namespace nvcuda;

#define B_TOT   8192
#define NTOK    49
#define CDIM    192
#define NH      6
#define HDIM    32
#define SCALE_F 0.17677669529663687f   // 1/sqrt(32)
#define QKV_ROWS (B_TOT * NTOK)        // 401408

// fp16 copies of the weights (converted by conv_w each call; deterministic)
__device__ __align__(16) __half g_wqkv[CDIM * 3 * CDIM];   // [192][576] row-major
__device__ __align__(16) __half g_wproj[CDIM * CDIM];      // [192][192] row-major
// fp16 qkv scratch: [B_*N][576] row-major (Q|K|V interleaved by column blocks)
__device__ __align__(16) __half g_qkv[QKV_ROWS * 3 * CDIM];

__global__ void conv_w(const float* __restrict__ wq, const float* __restrict__ wp) {
    int i = blockIdx.x * 256 + threadIdx.x;
    if (i < CDIM * 3 * CDIM) g_wqkv[i]  = __float2half_rn(wq[i]);
    if (i < CDIM * CDIM)     g_wproj[i] = __float2half_rn(wp[i]);
}

// ============================================================================
// Kernel 1: QKV projection GEMM.  qkv[401408, 576] = X[401408,192] @ Wqkv + b
// Grid: 3136 CTAs, each computes a 128-row strip over all 576 cols in 6
// chunks of 96. Warp w owns m-tile w (16 rows) x 6 n-tiles (register strip):
// A fragment loaded once per k-step, reused for 6 MMAs.
// ============================================================================
// smem: xs half[128][200] @0 (51200) | wsc half[192][104] @51200 (39936)
//       stage float 8*16*20 @91136 (10240)   -> total 101376
#define K1_SMEM 101376

__global__ void __launch_bounds__(256, 2)
qkv_gemm(const float* __restrict__ x, const float* __restrict__ bqkv)
{
    extern __shared__ __align__(128) char smem[];
    __half* xs    = (__half*)(smem);            // ld 200
    __half* wsc   = (__half*)(smem + 51200);    // ld 104
    float*  stage = (float*) (smem + 91136);    // per-warp 16x20

    const int tid  = threadIdx.x;
    const int w    = tid >> 5;
    const int lane = tid & 31;
    const int rbase0 = blockIdx.x * 128;

    // ---- load X strip (128x192 fp32) -> fp16 smem ----
    const float* xb = x + (size_t)rbase0 * CDIM;
    for (int i = tid; i < 6144; i += 256) {           // 128*192/4 float4s
        float4 v = ((const float4*)xb)[i];
        int r = i / 48, c4 = i % 48;                  // col = 4*c4
        __half2* dst = (__half2*)(xs + r * 200 + c4 * 4);
        dst[0] = __floats2half2_rn(v.x, v.y);
        dst[1] = __floats2half2_rn(v.z, v.w);
    }

    for (int nc = 0; nc < 6; nc++) {
        __syncthreads();   // previous chunk's compute done before restaging wsc
        // ---- stage W chunk: rows 0..191, cols nc*96..+95 ----
        for (int i = tid; i < 2304; i += 256) {        // 192 rows * 12 int4
            int row = i / 12, v8 = i % 12;
            const int4* s = (const int4*)(g_wqkv + row * 576 + nc * 96 + v8 * 8);
            *(int4*)(wsc + row * 104 + v8 * 8) = *s;
        }
        __syncthreads();

        wmma::fragment<wmma::accumulator, 16, 16, 16, float> c[6];
        #pragma unroll
        for (int j = 0; j < 6; j++) wmma::fill_fragment(c[j], 0.0f);

        #pragma unroll
        for (int kt = 0; kt < 12; kt++) {
            wmma::fragment<wmma::matrix_a, 16, 16, 16, __half, wmma::row_major> a;
            wmma::load_matrix_sync(a, xs + w * 16 * 200 + kt * 16, 200);
            #pragma unroll
            for (int j = 0; j < 6; j++) {
                wmma::fragment<wmma::matrix_b, 16, 16, 16, __half, wmma::row_major> bf;
                wmma::load_matrix_sync(bf, wsc + kt * 16 * 104 + j * 16, 104);
                wmma::mma_sync(c[j], a, bf, c[j]);
            }
        }

        // ---- epilogue: +bias, fp16, store to g_qkv ----
        float* st = stage + w * 320;                  // 16x20
        int rbase = rbase0 + w * 16;
        #pragma unroll
        for (int j = 0; j < 6; j++) {
            wmma::store_matrix_sync(st, c[j], 20, wmma::mem_row_major);
            __syncwarp();
            int cbase = nc * 96 + j * 16;
            for (int e = lane; e < 128; e += 32) {    // 16 rows x 8 half2
                int rr = e >> 3, cc = (e & 7) * 2;
                float v0 = st[rr * 20 + cc]     + bqkv[cbase + cc];
                float v1 = st[rr * 20 + cc + 1] + bqkv[cbase + cc + 1];
                *(__half2*)(g_qkv + (size_t)(rbase + rr) * 576 + cbase + cc) =
                    __floats2half2_rn(v0, v1);
            }
            __syncwarp();
        }
    }
}

// ============================================================================
// Kernel 2: fused attention + output projection, one CTA per batch item.
// Reads qkv rows from scratch; per-head QK^T, masked softmax, PV, and
// accumulates the output projection in register fragments across heads.
// ============================================================================
// smem: qkvs half[64][584] @0       (74752)
//       R union @74752: Ss f32[64][76] (19456) / stage 8*16*20 f32 (10240) /
//                       wp half[32][200] (12800)
//       Ps half[64][72] @94208 (9216) | Os half[64][40] @103424 (5120)
//       msk float[64] @108544 (256)  -> total 108800
#define K2_SMEM 108800

__global__ void __launch_bounds__(256, 2)
attn_proj(const int* __restrict__ mask, const float* __restrict__ bproj,
          float* __restrict__ out)
{
    extern __shared__ __align__(128) char smem[];
    __half* qkvs  = (__half*)(smem);                 // ld 584
    float*  Ss    = (float*) (smem + 74752);         // ld 76
    float*  stage = (float*) (smem + 74752);         // per-warp 16x20
    __half* wp    = (__half*)(smem + 74752);         // ld 200
    __half* Ps    = (__half*)(smem + 94208);         // ld 72
    __half* Os    = (__half*)(smem + 103424);        // ld 40
    float*  msk   = (float*) (smem + 108544);

    const int b    = blockIdx.x;
    const int tid  = threadIdx.x;
    const int w    = tid >> 5;
    const int lane = tid & 31;

    // ---- load qkv rows (49 x 576 fp16), zero-pad rows 49..63 ----
    const __half* src = g_qkv + (size_t)b * NTOK * 576;
    for (int i = tid; i < NTOK * 72; i += 256) {      // 49 rows * 72 int4
        int r = i / 72, v8 = i % 72;
        *(int4*)(qkvs + r * 584 + v8 * 8) = ((const int4*)(src + r * 576))[v8];
    }
    for (int i = tid; i < 15 * 73; i += 256) {        // pad rows full width
        int r = 49 + i / 73, v8 = i % 73;
        *(int4*)(qkvs + r * 584 + v8 * 8) = make_int4(0, 0, 0, 0);
    }
    if (tid < 64) {
        int valid = (tid < NTOK) ? (mask[b * NTOK + tid] != 0) : 0;
        msk[tid] = valid ? 1.0f : 0.0f;
    }

    wmma::fragment<wmma::accumulator, 16, 16, 16, float> cacc[6];
    #pragma unroll
    for (int j = 0; j < 6; j++) wmma::fill_fragment(cacc[j], 0.0f);
    const int mM = w >> 1;
    const int n0 = (w & 1) * 6;

    for (int h = 0; h < NH; h++) {
        const int qo = h * HDIM, ko = CDIM + h * HDIM, vo = 2 * CDIM + h * HDIM;
        __syncthreads();   // prior head done with R (wp) before Ss overwrite

        // ---- GEMM2: Ss[64][64] = (Q @ K^T) * scale ----
        {
            int n = w & 3, m0q = w >> 2;              // warp does m0q and m0q+2
            wmma::fragment<wmma::accumulator, 16, 16, 16, float> c0, c1;
            wmma::fill_fragment(c0, 0.0f);
            wmma::fill_fragment(c1, 0.0f);
            #pragma unroll
            for (int kt = 0; kt < 2; kt++) {
                wmma::fragment<wmma::matrix_b, 16, 16, 16, __half, wmma::col_major> bf;
                wmma::load_matrix_sync(bf, qkvs + n * 16 * 584 + ko + kt * 16, 584);
                wmma::fragment<wmma::matrix_a, 16, 16, 16, __half, wmma::row_major> a0, a1;
                wmma::load_matrix_sync(a0, qkvs + m0q * 16 * 584 + qo + kt * 16, 584);
                wmma::load_matrix_sync(a1, qkvs + (m0q + 2) * 16 * 584 + qo + kt * 16, 584);
                wmma::mma_sync(c0, a0, bf, c0);
                wmma::mma_sync(c1, a1, bf, c1);
            }
            #pragma unroll
            for (int i = 0; i < c0.num_elements; i++) { c0.x[i] *= SCALE_F; c1.x[i] *= SCALE_F; }
            wmma::store_matrix_sync(Ss + m0q * 16 * 76 + n * 16, c0, 76, wmma::mem_row_major);
            wmma::store_matrix_sync(Ss + (m0q + 2) * 16 * 76 + n * 16, c1, 76, wmma::mem_row_major);
        }
        __syncthreads();

        // ---- masked softmax -> Ps fp16 ----
        for (int r = w; r < 64; r += 8) {
            if (r < NTOK) {
                float v0 = (msk[lane]      != 0.0f) ? Ss[r * 76 + lane]      : -1e30f;
                float v1 = (msk[lane + 32] != 0.0f) ? Ss[r * 76 + lane + 32] : -1e30f;
                float mx = fmaxf(v0, v1);
                #pragma unroll
                for (int o = 16; o > 0; o >>= 1) mx = fmaxf(mx, __shfl_xor_sync(0xffffffffu, mx, o));
                float e0 = __expf(v0 - mx), e1 = __expf(v1 - mx);
                float sm = e0 + e1;
                #pragma unroll
                for (int o = 16; o > 0; o >>= 1) sm += __shfl_xor_sync(0xffffffffu, sm, o);
                float inv = 1.0f / sm;
                Ps[r * 72 + lane]      = __float2half_rn(e0 * inv);
                Ps[r * 72 + lane + 32] = __float2half_rn(e1 * inv);
            } else {
                Ps[r * 72 + lane]      = __float2half_rn(0.0f);
                Ps[r * 72 + lane + 32] = __float2half_rn(0.0f);
            }
        }
        __syncthreads();   // Ps ready; Ss region free for stage

        // ---- GEMM3: Os[64][32] = Ps @ V ----
        {
            int m = w >> 1, n = w & 1;
            wmma::fragment<wmma::accumulator, 16, 16, 16, float> c;
            wmma::fill_fragment(c, 0.0f);
            #pragma unroll
            for (int kt = 0; kt < 4; kt++) {
                wmma::fragment<wmma::matrix_a, 16, 16, 16, __half, wmma::row_major> a;
                wmma::fragment<wmma::matrix_b, 16, 16, 16, __half, wmma::row_major> bf;
                wmma::load_matrix_sync(a,  Ps + m * 16 * 72 + kt * 16, 72);
                wmma::load_matrix_sync(bf, qkvs + kt * 16 * 584 + vo + n * 16, 584);
                wmma::mma_sync(c, a, bf, c);
            }
            float* st = stage + w * 320;
            wmma::store_matrix_sync(st, c, 20, wmma::mem_row_major);
            __syncwarp();
            for (int e = lane; e < 256; e += 32) {
                int rr = e >> 4, cc = e & 15;
                Os[(m * 16 + rr) * 40 + n * 16 + cc] = __float2half_rn(st[rr * 20 + cc]);
            }
        }
        __syncthreads();   // Os ready; stage region free for wp

        // ---- stage per-head proj slice: wp[32][200] = w_proj[h*32..+31][:] ----
        for (int i = tid; i < 768; i += 256) {         // 32 rows * 24 int4
            int row = i / 24, v8 = i % 24;
            const int4* s = (const int4*)(g_wproj + (h * 32 + row) * 192 + v8 * 8);
            *(int4*)(wp + row * 200 + v8 * 8) = *s;
        }
        __syncthreads();

        // ---- GEMM4 (accumulate): cacc += Os[64][32] @ wp[32][192] ----
        {
            wmma::fragment<wmma::matrix_a, 16, 16, 16, __half, wmma::row_major> a[2];
            wmma::load_matrix_sync(a[0], Os + mM * 16 * 40, 40);
            wmma::load_matrix_sync(a[1], Os + mM * 16 * 40 + 16, 40);
            #pragma unroll
            for (int j = 0; j < 6; j++) {
                #pragma unroll
                for (int kt = 0; kt < 2; kt++) {
                    wmma::fragment<wmma::matrix_b, 16, 16, 16, __half, wmma::row_major> bf;
                    wmma::load_matrix_sync(bf, wp + kt * 16 * 200 + (n0 + j) * 16, 200);
                    wmma::mma_sync(cacc[j], a[kt], bf, cacc[j]);
                }
            }
        }
    }

    __syncthreads();  // all warps done reading wp before stage reuse

    // ---- epilogue: + b_proj, store rows < 49 ----
    float* ob = out + (size_t)b * (NTOK * CDIM);
    float* st = stage + w * 320;
    #pragma unroll
    for (int j = 0; j < 6; j++) {
        wmma::store_matrix_sync(st, cacc[j], 20, wmma::mem_row_major);
        __syncwarp();
        int ncol = (n0 + j) * 16;
        for (int e = lane; e < 256; e += 32) {
            int rr = e >> 4, cc = e & 15;
            int r = mM * 16 + rr;
            if (r < NTOK) ob[r * CDIM + ncol + cc] = st[rr * 20 + cc] + bproj[ncol + cc];
        }
        __syncwarp();
    }
}

extern "C" void kernel_launch(void* const* d_in, const int* in_sizes, int n_in,
                              void* d_out, int out_size)
{
    (void)in_sizes; (void)n_in; (void)out_size;
    const float* x    = (const float*)d_in[0];
    const int*   mask = (const int*)  d_in[1];
    const float* wq   = (const float*)d_in[2];
    const float* bq   = (const float*)d_in[3];
    const float* wpj  = (const float*)d_in[4];
    const float* bp   = (const float*)d_in[5];
    float* out = (float*)d_out;

    conv_w<<<(CDIM * 3 * CDIM + 255) / 256, 256>>>(wq, wpj);

    cudaFuncSetAttribute(qkv_gemm, cudaFuncAttributeMaxDynamicSharedMemorySize, K1_SMEM);
    qkv_gemm<<<QKV_ROWS / 128, 256, K1_SMEM>>>(x, bq);

    cudaFuncSetAttribute(attn_proj, cudaFuncAttributeMaxDynamicSharedMemorySize, K2_SMEM);
    attn_proj<<<B_TOT, 256, K2_SMEM>>>(mask, bp, out);
}

// round 5
// speedup vs baseline: 1.6011x; 1.1497x over previous
#include <cuda_runtime.h>
#include <cuda_fp16.h>
#include <mma.h>

using namespace nvcuda;

#define B_TOT   8192
#define NTOK    49
#define CDIM    192
#define NH      6
#define HDIM    32
#define SCALE_F 0.17677669529663687f   // 1/sqrt(32)
#define QKV_ROWS (B_TOT * NTOK)        // 401408

// fp16 copies of the weights (converted by conv_w each call; deterministic)
__device__ __align__(16) __half g_wqkv[CDIM * 3 * CDIM];   // [192][576] row-major
__device__ __align__(16) __half g_wproj[CDIM * CDIM];      // [192][192] row-major
// fp16 qkv scratch: [B_*N][576] row-major
__device__ __align__(16) __half g_qkv[QKV_ROWS * 3 * CDIM];

__global__ void conv_w(const float* __restrict__ wq, const float* __restrict__ wp) {
    int i = blockIdx.x * 256 + threadIdx.x;
    if (i < CDIM * 3 * CDIM) g_wqkv[i]  = __float2half_rn(wq[i]);
    if (i < CDIM * CDIM)     g_wproj[i] = __float2half_rn(wp[i]);
}

// ============================================================================
// Kernel 1: QKV projection GEMM (unchanged from round 2).
// ============================================================================
#define K1_SMEM 101376

__global__ void __launch_bounds__(256, 2)
qkv_gemm(const float* __restrict__ x, const float* __restrict__ bqkv)
{
    extern __shared__ __align__(128) char smem[];
    __half* xs    = (__half*)(smem);            // ld 200
    __half* wsc   = (__half*)(smem + 51200);    // ld 104
    float*  stage = (float*) (smem + 91136);    // per-warp 16x20

    const int tid  = threadIdx.x;
    const int w    = tid >> 5;
    const int lane = tid & 31;
    const int rbase0 = blockIdx.x * 128;

    const float* xb = x + (size_t)rbase0 * CDIM;
    for (int i = tid; i < 6144; i += 256) {
        float4 v = ((const float4*)xb)[i];
        int r = i / 48, c4 = i % 48;
        __half2* dst = (__half2*)(xs + r * 200 + c4 * 4);
        dst[0] = __floats2half2_rn(v.x, v.y);
        dst[1] = __floats2half2_rn(v.z, v.w);
    }

    for (int nc = 0; nc < 6; nc++) {
        __syncthreads();
        for (int i = tid; i < 2304; i += 256) {
            int row = i / 12, v8 = i % 12;
            const int4* s = (const int4*)(g_wqkv + row * 576 + nc * 96 + v8 * 8);
            *(int4*)(wsc + row * 104 + v8 * 8) = *s;
        }
        __syncthreads();

        wmma::fragment<wmma::accumulator, 16, 16, 16, float> c[6];
        #pragma unroll
        for (int j = 0; j < 6; j++) wmma::fill_fragment(c[j], 0.0f);

        #pragma unroll
        for (int kt = 0; kt < 12; kt++) {
            wmma::fragment<wmma::matrix_a, 16, 16, 16, __half, wmma::row_major> a;
            wmma::load_matrix_sync(a, xs + w * 16 * 200 + kt * 16, 200);
            #pragma unroll
            for (int j = 0; j < 6; j++) {
                wmma::fragment<wmma::matrix_b, 16, 16, 16, __half, wmma::row_major> bf;
                wmma::load_matrix_sync(bf, wsc + kt * 16 * 104 + j * 16, 104);
                wmma::mma_sync(c[j], a, bf, c[j]);
            }
        }

        float* st = stage + w * 320;
        int rbase = rbase0 + w * 16;
        #pragma unroll
        for (int j = 0; j < 6; j++) {
            wmma::store_matrix_sync(st, c[j], 20, wmma::mem_row_major);
            __syncwarp();
            int cbase = nc * 96 + j * 16;
            for (int e = lane; e < 128; e += 32) {
                int rr = e >> 3, cc = (e & 7) * 2;
                float v0 = st[rr * 20 + cc]     + bqkv[cbase + cc];
                float v1 = st[rr * 20 + cc + 1] + bqkv[cbase + cc + 1];
                *(__half2*)(g_qkv + (size_t)(rbase + rr) * 576 + cbase + cc) =
                    __floats2half2_rn(v0, v1);
            }
            __syncwarp();
        }
    }
}

// ============================================================================
// Kernel 2: fused attention + output projection, one CTA per batch item.
// Per-head Q|K|V staging (13.3KB); per-head outputs concatenated into
// Oall[64][192]; projection once at the end with cacc[3] register strips.
// smem 74.5KB, low persistent regs -> target 3 CTAs/SM.
// ============================================================================
// smem: qbuf half[64][104]  @0      13312
//       Ss  f32 [64][76]    @13312  19456  (union: stage 8*16*20 f32 = 10240)
//       Ps  half[64][72]    @32768   9216
//       Oall half[64][200]  @41984  25600
//       wp  half[32][104]   @67584   6656
//       msk f32 [64]        @74240    256  -> total 74496
#define K2_SMEM 74496

__global__ void __launch_bounds__(256, 3)
attn_proj(const int* __restrict__ mask, const float* __restrict__ bproj,
          float* __restrict__ out)
{
    extern __shared__ __align__(128) char smem[];
    __half* qbuf  = (__half*)(smem);                 // ld 104 (Q:0-31 K:32-63 V:64-95)
    float*  Ss    = (float*) (smem + 13312);         // ld 76
    float*  stage = (float*) (smem + 13312);         // per-warp 16x20 (union w/ Ss)
    __half* Ps    = (__half*)(smem + 32768);         // ld 72
    __half* Oall  = (__half*)(smem + 41984);         // ld 200
    __half* wp    = (__half*)(smem + 67584);         // ld 104
    float*  msk   = (float*) (smem + 74240);

    const int b    = blockIdx.x;
    const int tid  = threadIdx.x;
    const int w    = tid >> 5;
    const int lane = tid & 31;

    if (tid < 64) {
        int valid = (tid < NTOK) ? (mask[b * NTOK + tid] != 0) : 0;
        msk[tid] = valid ? 1.0f : 0.0f;
    }

    const __half* qkv_b = g_qkv + (size_t)b * NTOK * 576;

    for (int h = 0; h < NH; h++) {
        __syncthreads();   // prior head's GEMM3 done reading qbuf / writing Oall

        // ---- stage per-head slice: qbuf[64][96] = Q|K|V cols of head h ----
        // each row: 3 segments (Q,K,V) x 32 halves = 12 int4 per row
        for (int i = tid; i < NTOK * 12; i += 256) {
            int row = i / 12, j12 = i % 12;
            int seg = j12 >> 2, hv = j12 & 3;
            const int4* s = (const int4*)(qkv_b + row * 576 + seg * 192 + h * HDIM + hv * 8);
            *(int4*)(qbuf + row * 104 + seg * 32 + hv * 8) = *s;
        }
        for (int i = tid; i < 15 * 13; i += 256) {      // zero pad rows 49..63 full width
            int r = 49 + i / 13, v8 = i % 13;
            *(int4*)(qbuf + r * 104 + v8 * 8) = make_int4(0, 0, 0, 0);
        }
        __syncthreads();

        // ---- GEMM2: Ss[64][64] = (Q @ K^T) * scale ----
        {
            int n = w & 3, m0q = w >> 2;               // warp does m0q and m0q+2
            wmma::fragment<wmma::accumulator, 16, 16, 16, float> c0, c1;
            wmma::fill_fragment(c0, 0.0f);
            wmma::fill_fragment(c1, 0.0f);
            #pragma unroll
            for (int kt = 0; kt < 2; kt++) {
                wmma::fragment<wmma::matrix_b, 16, 16, 16, __half, wmma::col_major> bf;
                wmma::load_matrix_sync(bf, qbuf + n * 16 * 104 + 32 + kt * 16, 104);
                wmma::fragment<wmma::matrix_a, 16, 16, 16, __half, wmma::row_major> a0, a1;
                wmma::load_matrix_sync(a0, qbuf + m0q * 16 * 104 + kt * 16, 104);
                wmma::load_matrix_sync(a1, qbuf + (m0q + 2) * 16 * 104 + kt * 16, 104);
                wmma::mma_sync(c0, a0, bf, c0);
                wmma::mma_sync(c1, a1, bf, c1);
            }
            #pragma unroll
            for (int i = 0; i < c0.num_elements; i++) { c0.x[i] *= SCALE_F; c1.x[i] *= SCALE_F; }
            wmma::store_matrix_sync(Ss + m0q * 16 * 76 + n * 16, c0, 76, wmma::mem_row_major);
            wmma::store_matrix_sync(Ss + (m0q + 2) * 16 * 76 + n * 16, c1, 76, wmma::mem_row_major);
        }
        __syncthreads();

        // ---- masked softmax -> Ps fp16 ----
        for (int r = w; r < 64; r += 8) {
            if (r < NTOK) {
                float v0 = (msk[lane]      != 0.0f) ? Ss[r * 76 + lane]      : -1e30f;
                float v1 = (msk[lane + 32] != 0.0f) ? Ss[r * 76 + lane + 32] : -1e30f;
                float mx = fmaxf(v0, v1);
                #pragma unroll
                for (int o = 16; o > 0; o >>= 1) mx = fmaxf(mx, __shfl_xor_sync(0xffffffffu, mx, o));
                float e0 = __expf(v0 - mx), e1 = __expf(v1 - mx);
                float sm = e0 + e1;
                #pragma unroll
                for (int o = 16; o > 0; o >>= 1) sm += __shfl_xor_sync(0xffffffffu, sm, o);
                float inv = 1.0f / sm;
                Ps[r * 72 + lane]      = __float2half_rn(e0 * inv);
                Ps[r * 72 + lane + 32] = __float2half_rn(e1 * inv);
            } else {
                Ps[r * 72 + lane]      = __float2half_rn(0.0f);
                Ps[r * 72 + lane + 32] = __float2half_rn(0.0f);
            }
        }
        __syncthreads();   // Ps ready; Ss region free for stage

        // ---- GEMM3: Oall[64][h*32..+31] = Ps @ V ----
        {
            int m = w >> 1, n = w & 1;
            wmma::fragment<wmma::accumulator, 16, 16, 16, float> c;
            wmma::fill_fragment(c, 0.0f);
            #pragma unroll
            for (int kt = 0; kt < 4; kt++) {
                wmma::fragment<wmma::matrix_a, 16, 16, 16, __half, wmma::row_major> a;
                wmma::fragment<wmma::matrix_b, 16, 16, 16, __half, wmma::row_major> bf;
                wmma::load_matrix_sync(a,  Ps + m * 16 * 72 + kt * 16, 72);
                wmma::load_matrix_sync(bf, qbuf + kt * 16 * 104 + 64 + n * 16, 104);
                wmma::mma_sync(c, a, bf, c);
            }
            float* st = stage + w * 320;
            wmma::store_matrix_sync(st, c, 20, wmma::mem_row_major);
            __syncwarp();
            for (int e = lane; e < 128; e += 32) {      // 16 rows x 8 half2
                int rr = e >> 3, cc = (e & 7) * 2;
                *(__half2*)(Oall + (m * 16 + rr) * 200 + h * HDIM + n * 16 + cc) =
                    __floats2half2_rn(st[rr * 20 + cc], st[rr * 20 + cc + 1]);
            }
            __syncwarp();
        }
    }

    __syncthreads();  // Oall complete

    // ---- output projection: C[64][192] = Oall @ Wproj + bias ----
    float* ob = out + (size_t)b * (NTOK * CDIM);
    float* st = stage + w * 320;
    const int mM = w >> 1;

    #pragma unroll
    for (int half = 0; half < 2; half++) {
        wmma::fragment<wmma::accumulator, 16, 16, 16, float> cacc[3];
        #pragma unroll
        for (int j = 0; j < 3; j++) wmma::fill_fragment(cacc[j], 0.0f);
        const int nloc0 = (w & 1) * 3;                  // local n-tile base in wp
        const int nb = half * 6 + nloc0;                // global n-tile base

        for (int kc = 0; kc < 6; kc++) {
            __syncthreads();   // prior wp chunk fully consumed (and stage free 1st iter)
            for (int i = tid; i < 384; i += 256) {      // 32 rows * 12 int4
                int row = i / 12, v8 = i % 12;
                const int4* s = (const int4*)(g_wproj + (kc * 32 + row) * 192 + half * 96 + v8 * 8);
                *(int4*)(wp + row * 104 + v8 * 8) = *s;
            }
            __syncthreads();

            wmma::fragment<wmma::matrix_a, 16, 16, 16, __half, wmma::row_major> a[2];
            wmma::load_matrix_sync(a[0], Oall + mM * 16 * 200 + kc * 32,      200);
            wmma::load_matrix_sync(a[1], Oall + mM * 16 * 200 + kc * 32 + 16, 200);
            #pragma unroll
            for (int j = 0; j < 3; j++) {
                #pragma unroll
                for (int kt = 0; kt < 2; kt++) {
                    wmma::fragment<wmma::matrix_b, 16, 16, 16, __half, wmma::row_major> bf;
                    wmma::load_matrix_sync(bf, wp + kt * 16 * 104 + (nloc0 + j) * 16, 104);
                    wmma::mma_sync(cacc[j], a[kt], bf, cacc[j]);
                }
            }
        }

        // epilogue for this half: + b_proj, store rows < 49
        #pragma unroll
        for (int j = 0; j < 3; j++) {
            wmma::store_matrix_sync(st, cacc[j], 20, wmma::mem_row_major);
            __syncwarp();
            int ncol = (nb + j) * 16;
            for (int e = lane; e < 256; e += 32) {
                int rr = e >> 4, cc = e & 15;
                int r = mM * 16 + rr;
                if (r < NTOK) ob[r * CDIM + ncol + cc] = st[rr * 20 + cc] + bproj[ncol + cc];
            }
            __syncwarp();
        }
        __syncthreads();   // stage/wp free before next half restages
    }
}

extern "C" void kernel_launch(void* const* d_in, const int* in_sizes, int n_in,
                              void* d_out, int out_size)
{
    (void)in_sizes; (void)n_in; (void)out_size;
    const float* x    = (const float*)d_in[0];
    const int*   mask = (const int*)  d_in[1];
    const float* wq   = (const float*)d_in[2];
    const float* bq   = (const float*)d_in[3];
    const float* wpj  = (const float*)d_in[4];
    const float* bp   = (const float*)d_in[5];
    float* out = (float*)d_out;

    conv_w<<<(CDIM * 3 * CDIM + 255) / 256, 256>>>(wq, wpj);

    cudaFuncSetAttribute(qkv_gemm, cudaFuncAttributeMaxDynamicSharedMemorySize, K1_SMEM);
    qkv_gemm<<<QKV_ROWS / 128, 256, K1_SMEM>>>(x, bq);

    cudaFuncSetAttribute(attn_proj, cudaFuncAttributeMaxDynamicSharedMemorySize, K2_SMEM);
    attn_proj<<<B_TOT, 256, K2_SMEM>>>(mask, bp, out);
}

// round 7
// speedup vs baseline: 2.1602x; 1.3492x over previous
#include <cstdint>
#include <stdint.h>
#include <cuda_runtime.h>
#include <cuda_fp16.h>
#include <mma.h>

using namespace nvcuda;

#define B_TOT   8192
#define NTOK    49
#define CDIM    192
#define NH      6
#define HDIM    32
#define SCALE_F 0.17677669529663687f   // 1/sqrt(32)
#define QKV_ROWS (B_TOT * NTOK)        // 401408

// fp16 copies of the weights (converted by conv_w each call; deterministic)
__device__ __align__(16) __half g_wqkv[CDIM * 3 * CDIM];   // [192][576] row-major
__device__ __align__(16) __half g_wproj[CDIM * CDIM];      // [192][192] row-major
// fp16 qkv scratch: [B_*N][576] row-major
__device__ __align__(16) __half g_qkv[QKV_ROWS * 3 * CDIM];

__global__ void conv_w(const float* __restrict__ wq, const float* __restrict__ wp) {
    int i = blockIdx.x * 256 + threadIdx.x;
    if (i < CDIM * 3 * CDIM) g_wqkv[i]  = __float2half_rn(wq[i]);
    if (i < CDIM * CDIM)     g_wproj[i] = __float2half_rn(wp[i]);
}

// ---------------------------------------------------------------------------
// raw-PTX helpers
// ---------------------------------------------------------------------------
__device__ __forceinline__ unsigned smaddr(const void* p) {
    return (unsigned)__cvta_generic_to_shared(p);
}
__device__ __forceinline__ void ldsm4(unsigned& r0, unsigned& r1, unsigned& r2, unsigned& r3,
                                      unsigned a) {
    asm volatile("ldmatrix.sync.aligned.m8n8.x4.shared.b16 {%0,%1,%2,%3}, [%4];"
                 : "=r"(r0), "=r"(r1), "=r"(r2), "=r"(r3) : "r"(a));
}
__device__ __forceinline__ void ldsm4t(unsigned& r0, unsigned& r1, unsigned& r2, unsigned& r3,
                                       unsigned a) {
    asm volatile("ldmatrix.sync.aligned.m8n8.x4.trans.shared.b16 {%0,%1,%2,%3}, [%4];"
                 : "=r"(r0), "=r"(r1), "=r"(r2), "=r"(r3) : "r"(a));
}
__device__ __forceinline__ void mma16816(float* c,
                                         unsigned a0, unsigned a1, unsigned a2, unsigned a3,
                                         unsigned b0, unsigned b1) {
    asm volatile(
        "mma.sync.aligned.m16n8k16.row.col.f32.f16.f16.f32 "
        "{%0,%1,%2,%3},{%4,%5,%6,%7},{%8,%9},{%0,%1,%2,%3};"
        : "+f"(c[0]), "+f"(c[1]), "+f"(c[2]), "+f"(c[3])
        : "r"(a0), "r"(a1), "r"(a2), "r"(a3), "r"(b0), "r"(b1));
}
__device__ __forceinline__ unsigned pack_h2(float a, float b) {
    __half2 h = __floats2half2_rn(a, b);
    return *(unsigned*)&h;
}

// ============================================================================
// Kernel 1: QKV projection GEMM (unchanged — it works).
// ============================================================================
#define K1_SMEM 101376

__global__ void __launch_bounds__(256, 2)
qkv_gemm(const float* __restrict__ x, const float* __restrict__ bqkv)
{
    extern __shared__ __align__(128) char smem[];
    __half* xs    = (__half*)(smem);            // ld 200
    __half* wsc   = (__half*)(smem + 51200);    // ld 104
    float*  stage = (float*) (smem + 91136);    // per-warp 16x20

    const int tid  = threadIdx.x;
    const int w    = tid >> 5;
    const int lane = tid & 31;
    const int rbase0 = blockIdx.x * 128;

    const float* xb = x + (size_t)rbase0 * CDIM;
    for (int i = tid; i < 6144; i += 256) {
        float4 v = ((const float4*)xb)[i];
        int r = i / 48, c4 = i % 48;
        __half2* dst = (__half2*)(xs + r * 200 + c4 * 4);
        dst[0] = __floats2half2_rn(v.x, v.y);
        dst[1] = __floats2half2_rn(v.z, v.w);
    }

    for (int nc = 0; nc < 6; nc++) {
        __syncthreads();
        for (int i = tid; i < 2304; i += 256) {
            int row = i / 12, v8 = i % 12;
            const int4* s = (const int4*)(g_wqkv + row * 576 + nc * 96 + v8 * 8);
            *(int4*)(wsc + row * 104 + v8 * 8) = *s;
        }
        __syncthreads();

        wmma::fragment<wmma::accumulator, 16, 16, 16, float> c[6];
        #pragma unroll
        for (int j = 0; j < 6; j++) wmma::fill_fragment(c[j], 0.0f);

        #pragma unroll
        for (int kt = 0; kt < 12; kt++) {
            wmma::fragment<wmma::matrix_a, 16, 16, 16, __half, wmma::row_major> a;
            wmma::load_matrix_sync(a, xs + w * 16 * 200 + kt * 16, 200);
            #pragma unroll
            for (int j = 0; j < 6; j++) {
                wmma::fragment<wmma::matrix_b, 16, 16, 16, __half, wmma::row_major> bf;
                wmma::load_matrix_sync(bf, wsc + kt * 16 * 104 + j * 16, 104);
                wmma::mma_sync(c[j], a, bf, c[j]);
            }
        }

        float* st = stage + w * 320;
        int rbase = rbase0 + w * 16;
        #pragma unroll
        for (int j = 0; j < 6; j++) {
            wmma::store_matrix_sync(st, c[j], 20, wmma::mem_row_major);
            __syncwarp();
            int cbase = nc * 96 + j * 16;
            for (int e = lane; e < 128; e += 32) {
                int rr = e >> 3, cc = (e & 7) * 2;
                float v0 = st[rr * 20 + cc]     + bqkv[cbase + cc];
                float v1 = st[rr * 20 + cc + 1] + bqkv[cbase + cc + 1];
                *(__half2*)(g_qkv + (size_t)(rbase + rr) * 576 + cbase + cc) =
                    __floats2half2_rn(v0, v1);
            }
            __syncwarp();
        }
    }
}

// ============================================================================
// Kernel 2: fused attention + output projection, one CTA per batch item.
// Register-resident attention: 2 heads per phase (warps 0-3 head A, 4-7 head
// B); each warp owns a full 16x64 S strip -> softmax in registers (quad
// shuffles), P accumulator reinterpreted directly as mma A-fragments.
// ============================================================================
// smem: qbuf2 half 2x[64][104] @0      26624  (union: stage f32 8x16x20 = 10240)
//       Oall  half [64][200]   @26624  25600
//       wp    half [32][104]   @52224   6656
//       mbs   u32 [2]          @58880      8   -> total 59008
#define K2_SMEM 59008

__global__ void __launch_bounds__(256, 3)
attn_proj(const int* __restrict__ mask, const float* __restrict__ bproj,
          float* __restrict__ out)
{
    extern __shared__ __align__(128) char smem[];
    __half*   qbuf2 = (__half*)(smem);               // 2 heads, each ld 104 (Q|K|V)
    float*    stage = (float*) (smem);               // proj epilogue (union w/ qbuf2)
    __half*   Oall  = (__half*)(smem + 26624);       // ld 200
    __half*   wp    = (__half*)(smem + 52224);       // ld 104
    unsigned* mbs   = (unsigned*)(smem + 58880);

    const int b    = blockIdx.x;
    const int tid  = threadIdx.x;
    const int w    = tid >> 5;
    const int lane = tid & 31;
    const int q2   = 2 * (lane & 3);                 // col offset within 8-col tile

    // ---- mask -> 64-bit ballot in smem ----
    {
        int valid = 0;
        if (tid < 64) valid = (tid < NTOK) ? (mask[b * NTOK + tid] != 0) : 0;
        unsigned bal = __ballot_sync(0xffffffffu, valid);
        if (w < 2 && lane == 0) mbs[w] = bal;
    }
    __syncthreads();
    const unsigned mb0 = mbs[0], mb1 = mbs[1];

    const __half* qkv_b = g_qkv + (size_t)b * NTOK * 576;

    const int hh = w >> 2;                 // which head of the pair this warp works on
    const int m  = w & 3;                  // m-tile (16 q rows)
    __half* qh = qbuf2 + hh * 6656;        // 6656 halves = 13312 B per head buffer

    for (int hp = 0; hp < 3; hp++) {
        __syncthreads();   // prior pair's ldmatrix reads of qbuf2 complete

        // ---- stage 2 heads: qbuf[hx][64][96] = Q|K|V cols of head hp*2+hx ----
        for (int i = tid; i < 2 * NTOK * 12; i += 256) {
            int hx = i / (NTOK * 12);
            int j  = i - hx * (NTOK * 12);
            int row = j / 12, j12 = j % 12;
            int seg = j12 >> 2, hv = j12 & 3;
            int h = hp * 2 + hx;
            const int4* s = (const int4*)(qkv_b + row * 576 + seg * 192 + h * HDIM + hv * 8);
            *(int4*)(qbuf2 + hx * 6656 + row * 104 + seg * 32 + hv * 8) = *s;
        }
        for (int i = tid; i < 2 * 15 * 13; i += 256) {   // zero-pad rows 49..63
            int hx = i / 195, j = i - hx * 195;
            int r = 49 + j / 13, v8 = j % 13;
            *(int4*)(qbuf2 + hx * 6656 + r * 104 + v8 * 8) = make_int4(0, 0, 0, 0);
        }
        __syncthreads();

        // ---- GEMM2 in registers: S[16][64] = Q_tile @ K^T ----
        float s[32];                                   // 8 n-tiles x 4
        #pragma unroll
        for (int i = 0; i < 32; i++) s[i] = 0.0f;

        #pragma unroll
        for (int kt = 0; kt < 2; kt++) {               // d chunks of 16
            unsigned a0, a1, a2, a3;
            {
                int r = m * 16 + (lane & 7) + ((lane >> 3) & 1) * 8;
                int c = kt * 16 + (lane >> 4) * 8;
                ldsm4(a0, a1, a2, a3, smaddr(qh + r * 104 + c));
            }
            #pragma unroll
            for (int ng = 0; ng < 4; ng++) {           // token groups of 16
                unsigned b0, b1, b2, b3;
                int r = ng * 16 + (lane & 7) + (lane >> 4) * 8;
                int c = 32 + kt * 16 + ((lane >> 3) & 1) * 8;
                ldsm4(b0, b1, b2, b3, smaddr(qh + r * 104 + c));
                mma16816(s + (2 * ng) * 4,     a0, a1, a2, a3, b0, b1);
                mma16816(s + (2 * ng + 1) * 4, a0, a1, a2, a3, b2, b3);
            }
        }

        // ---- masked softmax in registers (rows rA = m*16+lane/4 and +8) ----
        float mxA = -1e30f, mxB = -1e30f;
        #pragma unroll
        for (int t = 0; t < 8; t++) {
            int c0 = 8 * t + q2;                       // even; pair never straddles 32
            unsigned vm = (c0 < 32) ? (mb0 >> c0) : (mb1 >> (c0 - 32));
            s[4 * t + 0] = (vm & 1) ? s[4 * t + 0] * SCALE_F : -1e30f;
            s[4 * t + 1] = (vm & 2) ? s[4 * t + 1] * SCALE_F : -1e30f;
            s[4 * t + 2] = (vm & 1) ? s[4 * t + 2] * SCALE_F : -1e30f;
            s[4 * t + 3] = (vm & 2) ? s[4 * t + 3] * SCALE_F : -1e30f;
            mxA = fmaxf(mxA, fmaxf(s[4 * t + 0], s[4 * t + 1]));
            mxB = fmaxf(mxB, fmaxf(s[4 * t + 2], s[4 * t + 3]));
        }
        mxA = fmaxf(mxA, __shfl_xor_sync(0xffffffffu, mxA, 1));
        mxA = fmaxf(mxA, __shfl_xor_sync(0xffffffffu, mxA, 2));
        mxB = fmaxf(mxB, __shfl_xor_sync(0xffffffffu, mxB, 1));
        mxB = fmaxf(mxB, __shfl_xor_sync(0xffffffffu, mxB, 2));

        float smA = 0.0f, smB = 0.0f;
        #pragma unroll
        for (int t = 0; t < 8; t++) {
            s[4 * t + 0] = __expf(s[4 * t + 0] - mxA);
            s[4 * t + 1] = __expf(s[4 * t + 1] - mxA);
            s[4 * t + 2] = __expf(s[4 * t + 2] - mxB);
            s[4 * t + 3] = __expf(s[4 * t + 3] - mxB);
            smA += s[4 * t + 0] + s[4 * t + 1];
            smB += s[4 * t + 2] + s[4 * t + 3];
        }
        smA += __shfl_xor_sync(0xffffffffu, smA, 1);
        smA += __shfl_xor_sync(0xffffffffu, smA, 2);
        smB += __shfl_xor_sync(0xffffffffu, smB, 1);
        smB += __shfl_xor_sync(0xffffffffu, smB, 2);
        const float invA = 1.0f / smA, invB = 1.0f / smB;

        // ---- P accumulator -> A-fragments (layout identity, no shuffles) ----
        unsigned pa[16];
        #pragma unroll
        for (int kc = 0; kc < 4; kc++) {
            float* t0 = s + (2 * kc) * 4;
            float* t1 = s + (2 * kc + 1) * 4;
            pa[4 * kc + 0] = pack_h2(t0[0] * invA, t0[1] * invA);
            pa[4 * kc + 1] = pack_h2(t0[2] * invB, t0[3] * invB);
            pa[4 * kc + 2] = pack_h2(t1[0] * invA, t1[1] * invA);
            pa[4 * kc + 3] = pack_h2(t1[2] * invB, t1[3] * invB);
        }

        // ---- GEMM3 in registers: O[16][32] = P @ V ----
        float o[16];
        #pragma unroll
        for (int i = 0; i < 16; i++) o[i] = 0.0f;
        #pragma unroll
        for (int kc = 0; kc < 4; kc++) {               // token chunks of 16
            #pragma unroll
            for (int nh = 0; nh < 2; nh++) {           // d halves of 16
                unsigned b0, b1, b2, b3;
                int r = kc * 16 + (lane & 7) + ((lane >> 3) & 1) * 8;
                int c = 64 + nh * 16 + (lane >> 4) * 8;
                ldsm4t(b0, b1, b2, b3, smaddr(qh + r * 104 + c));
                mma16816(o + (2 * nh) * 4,
                         pa[4 * kc + 0], pa[4 * kc + 1], pa[4 * kc + 2], pa[4 * kc + 3],
                         b0, b1);
                mma16816(o + (2 * nh + 1) * 4,
                         pa[4 * kc + 0], pa[4 * kc + 1], pa[4 * kc + 2], pa[4 * kc + 3],
                         b2, b3);
            }
        }

        // ---- store O tile to Oall (fp16) ----
        {
            int h  = hp * 2 + hh;
            int rA = m * 16 + (lane >> 2);
            #pragma unroll
            for (int t = 0; t < 4; t++) {
                int col = h * HDIM + 8 * t + q2;
                *(__half2*)(Oall + rA * 200 + col) =
                    __floats2half2_rn(o[4 * t + 0], o[4 * t + 1]);
                *(__half2*)(Oall + (rA + 8) * 200 + col) =
                    __floats2half2_rn(o[4 * t + 2], o[4 * t + 3]);
            }
        }
    }

    // ---- output projection: C[64][192] = Oall @ Wproj + bias (wmma) ----
    float* ob = out + (size_t)b * (NTOK * CDIM);
    float* st = stage + w * 320;
    const int mM = w >> 1;

    #pragma unroll
    for (int hseg = 0; hseg < 2; hseg++) {
        wmma::fragment<wmma::accumulator, 16, 16, 16, float> cacc[3];
        #pragma unroll
        for (int j = 0; j < 3; j++) wmma::fill_fragment(cacc[j], 0.0f);
        const int nloc0 = (w & 1) * 3;
        const int nb = hseg * 6 + nloc0;

        for (int kc = 0; kc < 6; kc++) {
            __syncthreads();   // prior wp chunk consumed; (kc=0) attention fully done
            for (int i = tid; i < 384; i += 256) {      // 32 rows * 12 int4
                int row = i / 12, v8 = i % 12;
                const int4* sp = (const int4*)(g_wproj + (kc * 32 + row) * 192 + hseg * 96 + v8 * 8);
                *(int4*)(wp + row * 104 + v8 * 8) = *sp;
            }
            __syncthreads();

            wmma::fragment<wmma::matrix_a, 16, 16, 16, __half, wmma::row_major> a[2];
            wmma::load_matrix_sync(a[0], Oall + mM * 16 * 200 + kc * 32,      200);
            wmma::load_matrix_sync(a[1], Oall + mM * 16 * 200 + kc * 32 + 16, 200);
            #pragma unroll
            for (int j = 0; j < 3; j++) {
                #pragma unroll
                for (int kt = 0; kt < 2; kt++) {
                    wmma::fragment<wmma::matrix_b, 16, 16, 16, __half, wmma::row_major> bf;
                    wmma::load_matrix_sync(bf, wp + kt * 16 * 104 + (nloc0 + j) * 16, 104);
                    wmma::mma_sync(cacc[j], a[kt], bf, cacc[j]);
                }
            }
        }

        // epilogue: + b_proj, store rows < 49
        #pragma unroll
        for (int j = 0; j < 3; j++) {
            wmma::store_matrix_sync(st, cacc[j], 20, wmma::mem_row_major);
            __syncwarp();
            int ncol = (nb + j) * 16;
            for (int e = lane; e < 256; e += 32) {
                int rr = e >> 4, cc = e & 15;
                int r = mM * 16 + rr;
                if (r < NTOK) ob[r * CDIM + ncol + cc] = st[rr * 20 + cc] + bproj[ncol + cc];
            }
            __syncwarp();
        }
        __syncthreads();   // stage/wp free before next hseg restages
    }
}

extern "C" void kernel_launch(void* const* d_in, const int* in_sizes, int n_in,
                              void* d_out, int out_size)
{
    (void)in_sizes; (void)n_in; (void)out_size;
    const float* x    = (const float*)d_in[0];
    const int*   mask = (const int*)  d_in[1];
    const float* wq   = (const float*)d_in[2];
    const float* bq   = (const float*)d_in[3];
    const float* wpj  = (const float*)d_in[4];
    const float* bp   = (const float*)d_in[5];
    float* out = (float*)d_out;

    conv_w<<<(CDIM * 3 * CDIM + 255) / 256, 256>>>(wq, wpj);

    cudaFuncSetAttribute(qkv_gemm, cudaFuncAttributeMaxDynamicSharedMemorySize, K1_SMEM);
    qkv_gemm<<<QKV_ROWS / 128, 256, K1_SMEM>>>(x, bq);

    cudaFuncSetAttribute(attn_proj, cudaFuncAttributeMaxDynamicSharedMemorySize, K2_SMEM);
    attn_proj<<<B_TOT, 256, K2_SMEM>>>(mask, bp, out);
}

// round 8
// speedup vs baseline: 2.5611x; 1.1856x over previous
#include <cstdint>
#include <stdint.h>
#include <cuda_runtime.h>
#include <cuda_fp16.h>

#define B_TOT   8192
#define NTOK    49
#define CDIM    192
#define NH      6
#define HDIM    32
#define SCALE_F 0.17677669529663687f   // 1/sqrt(32)
#define QKV_ROWS (B_TOT * NTOK)        // 401408

// fp16 copies of the weights (converted by conv_w each call; deterministic)
__device__ __align__(16) __half g_wqkv[CDIM * 3 * CDIM];   // [192][576] row-major
__device__ __align__(16) __half g_wproj[CDIM * CDIM];      // [192][192] row-major
// fp16 qkv scratch: [B_*N][576] row-major
__device__ __align__(16) __half g_qkv[QKV_ROWS * 3 * CDIM];

__global__ void conv_w(const float* __restrict__ wq, const float* __restrict__ wp) {
    int i = blockIdx.x * 256 + threadIdx.x;
    if (i < CDIM * 3 * CDIM) g_wqkv[i]  = __float2half_rn(wq[i]);
    if (i < CDIM * CDIM)     g_wproj[i] = __float2half_rn(wp[i]);
}

// ---------------------------------------------------------------------------
// raw-PTX helpers
// ---------------------------------------------------------------------------
__device__ __forceinline__ unsigned smaddr(const void* p) {
    return (unsigned)__cvta_generic_to_shared(p);
}
__device__ __forceinline__ void ldsm4(unsigned& r0, unsigned& r1, unsigned& r2, unsigned& r3,
                                      unsigned a) {
    asm volatile("ldmatrix.sync.aligned.m8n8.x4.shared.b16 {%0,%1,%2,%3}, [%4];"
                 : "=r"(r0), "=r"(r1), "=r"(r2), "=r"(r3) : "r"(a));
}
__device__ __forceinline__ void ldsm4t(unsigned& r0, unsigned& r1, unsigned& r2, unsigned& r3,
                                       unsigned a) {
    asm volatile("ldmatrix.sync.aligned.m8n8.x4.trans.shared.b16 {%0,%1,%2,%3}, [%4];"
                 : "=r"(r0), "=r"(r1), "=r"(r2), "=r"(r3) : "r"(a));
}
__device__ __forceinline__ void mma16816(float* c,
                                         unsigned a0, unsigned a1, unsigned a2, unsigned a3,
                                         unsigned b0, unsigned b1) {
    asm volatile(
        "mma.sync.aligned.m16n8k16.row.col.f32.f16.f16.f32 "
        "{%0,%1,%2,%3},{%4,%5,%6,%7},{%8,%9},{%0,%1,%2,%3};"
        : "+f"(c[0]), "+f"(c[1]), "+f"(c[2]), "+f"(c[3])
        : "r"(a0), "r"(a1), "r"(a2), "r"(a3), "r"(b0), "r"(b1));
}
__device__ __forceinline__ unsigned pack_h2(float a, float b) {
    __half2 h = __floats2half2_rn(a, b);
    return *(unsigned*)&h;
}

// ============================================================================
// Kernel 1: QKV projection GEMM, raw mma.
// 3136 CTAs x 256 thr; warp owns 16 rows. A (16x192) loaded ONCE from gmem
// directly into register A-fragments (no smem, no ldmatrix); 6 weight chunks
// of 96 cols staged in smem; C stored directly to g_qkv as half2 (+bias).
// smem: wsc half[192][104] = 39936 B
// ============================================================================
#define K1_SMEM 39936

__global__ void __launch_bounds__(256, 2)
qkv_gemm(const float* __restrict__ x, const float* __restrict__ bqkv)
{
    extern __shared__ __align__(128) char smem[];
    __half* wsc = (__half*)smem;                    // ld 104

    const int tid  = threadIdx.x;
    const int w    = tid >> 5;
    const int lane = tid & 31;
    const int rbase = blockIdx.x * 128 + w * 16;
    const int c0 = 2 * (lane & 3);

    // ---- A-fragments straight from gmem (fp32 -> fp16), held across chunks ----
    unsigned A[12][4];
    {
        const int r0 = rbase + (lane >> 2);
        const float* xr0 = x + (size_t)r0 * CDIM;
        const float* xr8 = xr0 + 8 * CDIM;
        #pragma unroll
        for (int kt = 0; kt < 12; kt++) {
            int c = kt * 16 + c0;
            float2 v;
            v = *(const float2*)(xr0 + c);     A[kt][0] = pack_h2(v.x, v.y);
            v = *(const float2*)(xr8 + c);     A[kt][1] = pack_h2(v.x, v.y);
            v = *(const float2*)(xr0 + c + 8); A[kt][2] = pack_h2(v.x, v.y);
            v = *(const float2*)(xr8 + c + 8); A[kt][3] = pack_h2(v.x, v.y);
        }
    }

    for (int nc = 0; nc < 6; nc++) {
        __syncthreads();   // prior chunk's ldsm reads of wsc complete
        for (int i = tid; i < 2304; i += 256) {      // 192 rows * 12 int4
            int row = i / 12, v8 = i % 12;
            const int4* s = (const int4*)(g_wqkv + row * 576 + nc * 96 + v8 * 8);
            *(int4*)(wsc + row * 104 + v8 * 8) = *s;
        }
        __syncthreads();

        float C[12][4];
        #pragma unroll
        for (int n = 0; n < 12; n++)
            #pragma unroll
            for (int e = 0; e < 4; e++) C[n][e] = 0.0f;

        #pragma unroll
        for (int kt = 0; kt < 12; kt++) {
            int rB = kt * 16 + (lane & 7) + ((lane >> 3) & 1) * 8;
            #pragma unroll
            for (int np = 0; np < 6; np++) {
                unsigned b0, b1, b2, b3;
                int cB = np * 16 + (lane >> 4) * 8;
                ldsm4t(b0, b1, b2, b3, smaddr(wsc + rB * 104 + cB));
                mma16816(C[2 * np],     A[kt][0], A[kt][1], A[kt][2], A[kt][3], b0, b1);
                mma16816(C[2 * np + 1], A[kt][0], A[kt][1], A[kt][2], A[kt][3], b2, b3);
            }
        }

        // ---- epilogue: +bias, fp16, direct global store ----
        {
            int orow = rbase + (lane >> 2);
            __half* g0 = g_qkv + (size_t)orow * 576 + nc * 96;
            __half* g8 = g0 + (size_t)8 * 576;
            #pragma unroll
            for (int n = 0; n < 12; n++) {
                int col = 8 * n + c0;
                float2 bb = *(const float2*)(bqkv + nc * 96 + col);
                *(__half2*)(g0 + col) = __floats2half2_rn(C[n][0] + bb.x, C[n][1] + bb.y);
                *(__half2*)(g8 + col) = __floats2half2_rn(C[n][2] + bb.x, C[n][3] + bb.y);
            }
        }
    }
}

// ============================================================================
// Kernel 2: fused attention + output projection, one CTA per batch item.
// Attention identical to round 7 (register-resident, 2 heads/phase).
// Projection now raw mma: each 96-col half of Wproj staged ONCE (39.9KB,
// unioned over qbuf2), C stored directly to out (+bias).
// ============================================================================
// smem: Oall  half [64][200]   @0      25600
//       qbuf2 half 2x[64][104] @25600  26624  (attention)   -> ends 52224
//       wp    half [192][104]  @25600  39936  (projection)  -> ends 65536
//       mbs   u32 [2]          @65536      8  -> total 65544 (pad to 65600)
#define K2_SMEM 65600

__global__ void __launch_bounds__(256, 3)
attn_proj(const int* __restrict__ mask, const float* __restrict__ bproj,
          float* __restrict__ out)
{
    extern __shared__ __align__(128) char smem[];
    __half*   Oall  = (__half*)(smem);               // ld 200
    __half*   qbuf2 = (__half*)(smem + 25600);       // 2 heads, each ld 104 (Q|K|V)
    __half*   wp    = (__half*)(smem + 25600);       // ld 104 (union w/ qbuf2)
    unsigned* mbs   = (unsigned*)(smem + 65536);

    const int b    = blockIdx.x;
    const int tid  = threadIdx.x;
    const int w    = tid >> 5;
    const int lane = tid & 31;
    const int q2   = 2 * (lane & 3);                 // col offset within 8-col tile

    // ---- mask -> 64-bit ballot in smem ----
    {
        int valid = 0;
        if (tid < 64) valid = (tid < NTOK) ? (mask[b * NTOK + tid] != 0) : 0;
        unsigned bal = __ballot_sync(0xffffffffu, valid);
        if (w < 2 && lane == 0) mbs[w] = bal;
    }
    __syncthreads();
    const unsigned mb0 = mbs[0], mb1 = mbs[1];

    const __half* qkv_b = g_qkv + (size_t)b * NTOK * 576;

    const int hh = w >> 2;                 // which head of the pair this warp works on
    const int m  = w & 3;                  // m-tile (16 q rows)
    __half* qh = qbuf2 + hh * 6656;        // 6656 halves = 13312 B per head buffer

    for (int hp = 0; hp < 3; hp++) {
        __syncthreads();   // prior pair's ldmatrix reads of qbuf2 complete

        // ---- stage 2 heads: qbuf[hx][64][96] = Q|K|V cols of head hp*2+hx ----
        for (int i = tid; i < 2 * NTOK * 12; i += 256) {
            int hx = i / (NTOK * 12);
            int j  = i - hx * (NTOK * 12);
            int row = j / 12, j12 = j % 12;
            int seg = j12 >> 2, hv = j12 & 3;
            int h = hp * 2 + hx;
            const int4* s = (const int4*)(qkv_b + row * 576 + seg * 192 + h * HDIM + hv * 8);
            *(int4*)(qbuf2 + hx * 6656 + row * 104 + seg * 32 + hv * 8) = *s;
        }
        for (int i = tid; i < 2 * 15 * 13; i += 256) {   // zero-pad rows 49..63
            int hx = i / 195, j = i - hx * 195;
            int r = 49 + j / 13, v8 = j % 13;
            *(int4*)(qbuf2 + hx * 6656 + r * 104 + v8 * 8) = make_int4(0, 0, 0, 0);
        }
        __syncthreads();

        // ---- GEMM2 in registers: S[16][64] = Q_tile @ K^T ----
        float s[32];                                   // 8 n-tiles x 4
        #pragma unroll
        for (int i = 0; i < 32; i++) s[i] = 0.0f;

        #pragma unroll
        for (int kt = 0; kt < 2; kt++) {               // d chunks of 16
            unsigned a0, a1, a2, a3;
            {
                int r = m * 16 + (lane & 7) + ((lane >> 3) & 1) * 8;
                int c = kt * 16 + (lane >> 4) * 8;
                ldsm4(a0, a1, a2, a3, smaddr(qh + r * 104 + c));
            }
            #pragma unroll
            for (int ng = 0; ng < 4; ng++) {           // token groups of 16
                unsigned b0, b1, b2, b3;
                int r = ng * 16 + (lane & 7) + (lane >> 4) * 8;
                int c = 32 + kt * 16 + ((lane >> 3) & 1) * 8;
                ldsm4(b0, b1, b2, b3, smaddr(qh + r * 104 + c));
                mma16816(s + (2 * ng) * 4,     a0, a1, a2, a3, b0, b1);
                mma16816(s + (2 * ng + 1) * 4, a0, a1, a2, a3, b2, b3);
            }
        }

        // ---- masked softmax in registers (rows rA = m*16+lane/4 and +8) ----
        float mxA = -1e30f, mxB = -1e30f;
        #pragma unroll
        for (int t = 0; t < 8; t++) {
            int c0 = 8 * t + q2;                       // even; pair never straddles 32
            unsigned vm = (c0 < 32) ? (mb0 >> c0) : (mb1 >> (c0 - 32));
            s[4 * t + 0] = (vm & 1) ? s[4 * t + 0] * SCALE_F : -1e30f;
            s[4 * t + 1] = (vm & 2) ? s[4 * t + 1] * SCALE_F : -1e30f;
            s[4 * t + 2] = (vm & 1) ? s[4 * t + 2] * SCALE_F : -1e30f;
            s[4 * t + 3] = (vm & 2) ? s[4 * t + 3] * SCALE_F : -1e30f;
            mxA = fmaxf(mxA, fmaxf(s[4 * t + 0], s[4 * t + 1]));
            mxB = fmaxf(mxB, fmaxf(s[4 * t + 2], s[4 * t + 3]));
        }
        mxA = fmaxf(mxA, __shfl_xor_sync(0xffffffffu, mxA, 1));
        mxA = fmaxf(mxA, __shfl_xor_sync(0xffffffffu, mxA, 2));
        mxB = fmaxf(mxB, __shfl_xor_sync(0xffffffffu, mxB, 1));
        mxB = fmaxf(mxB, __shfl_xor_sync(0xffffffffu, mxB, 2));

        float smA = 0.0f, smB = 0.0f;
        #pragma unroll
        for (int t = 0; t < 8; t++) {
            s[4 * t + 0] = __expf(s[4 * t + 0] - mxA);
            s[4 * t + 1] = __expf(s[4 * t + 1] - mxA);
            s[4 * t + 2] = __expf(s[4 * t + 2] - mxB);
            s[4 * t + 3] = __expf(s[4 * t + 3] - mxB);
            smA += s[4 * t + 0] + s[4 * t + 1];
            smB += s[4 * t + 2] + s[4 * t + 3];
        }
        smA += __shfl_xor_sync(0xffffffffu, smA, 1);
        smA += __shfl_xor_sync(0xffffffffu, smA, 2);
        smB += __shfl_xor_sync(0xffffffffu, smB, 1);
        smB += __shfl_xor_sync(0xffffffffu, smB, 2);
        const float invA = 1.0f / smA, invB = 1.0f / smB;

        // ---- P accumulator -> A-fragments (layout identity, no shuffles) ----
        unsigned pa[16];
        #pragma unroll
        for (int kc = 0; kc < 4; kc++) {
            float* t0 = s + (2 * kc) * 4;
            float* t1 = s + (2 * kc + 1) * 4;
            pa[4 * kc + 0] = pack_h2(t0[0] * invA, t0[1] * invA);
            pa[4 * kc + 1] = pack_h2(t0[2] * invB, t0[3] * invB);
            pa[4 * kc + 2] = pack_h2(t1[0] * invA, t1[1] * invA);
            pa[4 * kc + 3] = pack_h2(t1[2] * invB, t1[3] * invB);
        }

        // ---- GEMM3 in registers: O[16][32] = P @ V ----
        float o[16];
        #pragma unroll
        for (int i = 0; i < 16; i++) o[i] = 0.0f;
        #pragma unroll
        for (int kc = 0; kc < 4; kc++) {               // token chunks of 16
            #pragma unroll
            for (int nh = 0; nh < 2; nh++) {           // d halves of 16
                unsigned b0, b1, b2, b3;
                int r = kc * 16 + (lane & 7) + ((lane >> 3) & 1) * 8;
                int c = 64 + nh * 16 + (lane >> 4) * 8;
                ldsm4t(b0, b1, b2, b3, smaddr(qh + r * 104 + c));
                mma16816(o + (2 * nh) * 4,
                         pa[4 * kc + 0], pa[4 * kc + 1], pa[4 * kc + 2], pa[4 * kc + 3],
                         b0, b1);
                mma16816(o + (2 * nh + 1) * 4,
                         pa[4 * kc + 0], pa[4 * kc + 1], pa[4 * kc + 2], pa[4 * kc + 3],
                         b2, b3);
            }
        }

        // ---- store O tile to Oall (fp16) ----
        {
            int h  = hp * 2 + hh;
            int rA = m * 16 + (lane >> 2);
            #pragma unroll
            for (int t = 0; t < 4; t++) {
                int col = h * HDIM + 8 * t + q2;
                *(__half2*)(Oall + rA * 200 + col) =
                    __floats2half2_rn(o[4 * t + 0], o[4 * t + 1]);
                *(__half2*)(Oall + (rA + 8) * 200 + col) =
                    __floats2half2_rn(o[4 * t + 2], o[4 * t + 3]);
            }
        }
    }

    // ---- output projection: C[64][192] = Oall @ Wproj + bias (raw mma) ----
    float* ob = out + (size_t)b * (NTOK * CDIM);
    const int rt = w >> 1;                 // row tile (16 rows)
    const int cq = w & 1;                  // 48-col quarter within the 96-col half

    #pragma unroll
    for (int hseg = 0; hseg < 2; hseg++) {
        __syncthreads();   // attention O stores (hseg 0) / prior wp reads (hseg 1) done
        for (int i = tid; i < 2304; i += 256) {       // 192 rows * 12 int4
            int row = i / 12, v8 = i % 12;
            const int4* sp = (const int4*)(g_wproj + row * 192 + hseg * 96 + v8 * 8);
            *(int4*)(wp + row * 104 + v8 * 8) = *sp;
        }
        __syncthreads();

        float C[6][4];
        #pragma unroll
        for (int n = 0; n < 6; n++)
            #pragma unroll
            for (int e = 0; e < 4; e++) C[n][e] = 0.0f;

        #pragma unroll
        for (int kt = 0; kt < 12; kt++) {
            unsigned a0, a1, a2, a3;
            {
                int rA = rt * 16 + (lane & 7) + ((lane >> 3) & 1) * 8;
                int cA = kt * 16 + (lane >> 4) * 8;
                ldsm4(a0, a1, a2, a3, smaddr(Oall + rA * 200 + cA));
            }
            int rB = kt * 16 + (lane & 7) + ((lane >> 3) & 1) * 8;
            #pragma unroll
            for (int np = 0; np < 3; np++) {
                unsigned b0, b1, b2, b3;
                int cB = cq * 48 + np * 16 + (lane >> 4) * 8;
                ldsm4t(b0, b1, b2, b3, smaddr(wp + rB * 104 + cB));
                mma16816(C[2 * np],     a0, a1, a2, a3, b0, b1);
                mma16816(C[2 * np + 1], a0, a1, a2, a3, b2, b3);
            }
        }

        // ---- epilogue: +bias, direct f32 stores, rows < 49 ----
        {
            int r = rt * 16 + (lane >> 2);
            #pragma unroll
            for (int n = 0; n < 6; n++) {
                int col = hseg * 96 + cq * 48 + 8 * n + q2;
                float2 bb = *(const float2*)(bproj + col);
                if (r < NTOK) {
                    ob[r * CDIM + col]     = C[n][0] + bb.x;
                    ob[r * CDIM + col + 1] = C[n][1] + bb.y;
                }
                if (r + 8 < NTOK) {
                    ob[(r + 8) * CDIM + col]     = C[n][2] + bb.x;
                    ob[(r + 8) * CDIM + col + 1] = C[n][3] + bb.y;
                }
            }
        }
    }
}

extern "C" void kernel_launch(void* const* d_in, const int* in_sizes, int n_in,
                              void* d_out, int out_size)
{
    (void)in_sizes; (void)n_in; (void)out_size;
    const float* x    = (const float*)d_in[0];
    const int*   mask = (const int*)  d_in[1];
    const float* wq   = (const float*)d_in[2];
    const float* bq   = (const float*)d_in[3];
    const float* wpj  = (const float*)d_in[4];
    const float* bp   = (const float*)d_in[5];
    float* out = (float*)d_out;

    conv_w<<<(CDIM * 3 * CDIM + 255) / 256, 256>>>(wq, wpj);

    cudaFuncSetAttribute(qkv_gemm, cudaFuncAttributeMaxDynamicSharedMemorySize, K1_SMEM);
    qkv_gemm<<<QKV_ROWS / 128, 256, K1_SMEM>>>(x, bq);

    cudaFuncSetAttribute(attn_proj, cudaFuncAttributeMaxDynamicSharedMemorySize, K2_SMEM);
    attn_proj<<<B_TOT, 256, K2_SMEM>>>(mask, bp, out);
}